// round 6
// baseline (speedup 1.0000x reference)
#include <cuda_runtime.h>

// Problem constants (fixed by the dataset)
#define Bc   8
#define Nc   6
#define Mc   64
#define Vc   32000
#define Tc   8
#define NP1  7            // N+1 template span dim
#define NV4  (Vc/4)       // 8000 float4 per row
#define CH   8            // V chunks per (b,m)
#define CHUNK (NV4/CH)    // 1000 float4 per chunk
#define THR  256

// Tiny scratch (device globals — no allocation allowed).
// g_any is written unconditionally by every chunk each run -> no init needed.
__device__ int g_any[Bc * Tc * Mc * CH];  // 1 if chunk saw out_v > out0 for (b,t,m,c)

// ---------------------------------------------------------------------------
// Kernel 1: per (b,m,chunk) stream dec once; write out_0 to d_out; per t flag
// whether any out_v > out0 in this chunk. Weights in registers, loads batched
// 2-deep, streaming cache hints (zero-reuse data).
// ---------------------------------------------------------------------------
template <int S>
__device__ __forceinline__ void amax_body(
    const float* __restrict__ dec,
    const float (*__restrict__ w)[NP1],   // shared masked template [T][NP1]
    int* smask,
    int b, int m, int c, int tid,
    float* __restrict__ out)
{
    constexpr int SS = (S > 0) ? S : 1;
    float wl[Tc][SS];
    float w0[Tc];
#pragma unroll
    for (int t = 0; t < Tc; ++t) {
        w0[t] = w[t][0];
#pragma unroll
        for (int s = 0; s < S; ++s) wl[t][s] = w[t][s + 1];
    }

    // out0[t] — same fmaf chain as the main loop so the v=0 element in chunk 0
    // compares exactly equal (never strictly greater).
    float d0[SS];
#pragma unroll
    for (int s = 0; s < S; ++s) d0[s] = __ldg(dec + ((b * Nc + s) * Mc + m) * Vc);
    float out0[Tc];
#pragma unroll
    for (int t = 0; t < Tc; ++t) {
        float a = 0.f;
#pragma unroll
        for (int s = 0; s < S; ++s) a = fmaf(wl[t][s], d0[s], a);
        if (m == 0) a += w0[t];
        out0[t] = a;
    }

    const float4* dp[SS];
#pragma unroll
    for (int s = 0; s < S; ++s)
        dp[s] = (const float4*)(dec + ((b * Nc + s) * Mc + m) * Vc);
    float4* o = (float4*)(out + (b * Mc + m) * Vc);

    const int base = c * CHUNK;
    unsigned mask = 0;

    int i = tid;
    // main loop: 2 elements per trip, 2*S streaming loads front-batched
    for (; i + THR < CHUNK; i += 2 * THR) {
        int g0 = base + i;
        int g1 = g0 + THR;
        float4 da[SS], db[SS];
#pragma unroll
        for (int s = 0; s < S; ++s) da[s] = __ldcs(&dp[s][g0]);
#pragma unroll
        for (int s = 0; s < S; ++s) db[s] = __ldcs(&dp[s][g1]);

#pragma unroll
        for (int t = 0; t < Tc; ++t) {
            float ax = 0.f, ay = 0.f, az = 0.f, aw = 0.f;
            float bx = 0.f, by = 0.f, bz = 0.f, bw = 0.f;
#pragma unroll
            for (int s = 0; s < S; ++s) {
                ax = fmaf(wl[t][s], da[s].x, ax);
                ay = fmaf(wl[t][s], da[s].y, ay);
                az = fmaf(wl[t][s], da[s].z, az);
                aw = fmaf(wl[t][s], da[s].w, aw);
                bx = fmaf(wl[t][s], db[s].x, bx);
                by = fmaf(wl[t][s], db[s].y, by);
                bz = fmaf(wl[t][s], db[s].z, bz);
                bw = fmaf(wl[t][s], db[s].w, bw);
            }
            if (m == 0 && g0 == 0) ax += w0[t];   // pad one-hot (chunk 0 only)
            if (t == 0) {
                float4 r; r.x = ax; r.y = ay; r.z = az; r.w = aw;
                __stcs(&o[g0], r);
                float4 q; q.x = bx; q.y = by; q.z = bz; q.w = bw;
                __stcs(&o[g1], q);
            }
            float m1 = fmaxf(fmaxf(fmaxf(ax, ay), fmaxf(az, aw)),
                             fmaxf(fmaxf(bx, by), fmaxf(bz, bw)));
            mask |= (m1 > out0[t]) ? (1u << t) : 0u;
        }
    }
    // tail: at most one element left per thread
    if (i < CHUNK) {
        int gi = base + i;
        float4 da[SS];
#pragma unroll
        for (int s = 0; s < S; ++s) da[s] = __ldcs(&dp[s][gi]);
#pragma unroll
        for (int t = 0; t < Tc; ++t) {
            float ax = 0.f, ay = 0.f, az = 0.f, aw = 0.f;
#pragma unroll
            for (int s = 0; s < S; ++s) {
                ax = fmaf(wl[t][s], da[s].x, ax);
                ay = fmaf(wl[t][s], da[s].y, ay);
                az = fmaf(wl[t][s], da[s].z, az);
                aw = fmaf(wl[t][s], da[s].w, aw);
            }
            if (m == 0 && gi == 0) ax += w0[t];
            if (t == 0) {
                float4 r; r.x = ax; r.y = ay; r.z = az; r.w = aw;
                __stcs(&o[gi], r);
            }
            float m1 = fmaxf(fmaxf(ax, ay), fmaxf(az, aw));
            mask |= (m1 > out0[t]) ? (1u << t) : 0u;
        }
    }

    unsigned wm = __reduce_or_sync(0xffffffffu, mask);
    if ((tid & 31) == 0) atomicOr(smask, (int)wm);
    __syncthreads();
    if (tid < Tc)
        g_any[((b * Tc + tid) * Mc + m) * CH + c] = (*smask >> tid) & 1;
}

__global__ __launch_bounds__(THR, 2) void k_amax(
    const float* __restrict__ dec,
    const float* __restrict__ tmpl,
    const int*   __restrict__ spans,
    float*       __restrict__ out)
{
    int bid = blockIdx.x;
    int c = bid & (CH - 1);
    int m = (bid >> 3) & (Mc - 1);
    int b = bid >> 9;
    int tid = threadIdx.x;

    __shared__ float w[Tc][NP1];
    __shared__ int smask;
    if (tid == 0) smask = 0;

    int S = spans[b];   // 0..5, uniform per block
    if (tid < Tc * NP1) {
        int t = tid / NP1, s = tid % NP1;
        w[t][s] = (s <= S) ? tmpl[(b * Tc + t) * NP1 + s] : 0.f;
    }
    __syncthreads();

    switch (S) {
        case 0: amax_body<0>(dec, w, &smask, b, m, c, tid, out); break;
        case 1: amax_body<1>(dec, w, &smask, b, m, c, tid, out); break;
        case 2: amax_body<2>(dec, w, &smask, b, m, c, tid, out); break;
        case 3: amax_body<3>(dec, w, &smask, b, m, c, tid, out); break;
        case 4: amax_body<4>(dec, w, &smask, b, m, c, tid, out); break;
        default: amax_body<5>(dec, w, &smask, b, m, c, tid, out); break;
    }
}

// ---------------------------------------------------------------------------
// Kernel 2: fixup with inlined ballot scan. Warp 0 of each (b,m) block
// recomputes the T-step copy scan from g_any (cheap, L2-resident), then the
// block rewrites its row only if the map differs from identity (t=0, m).
// ---------------------------------------------------------------------------
template <int S>
__device__ __forceinline__ void row_body(
    const float* __restrict__ dec,
    const float* __restrict__ tmpl,
    int b, int st, int sm, float4* __restrict__ o, int tid)
{
    constexpr int SS = (S > 0) ? S : 1;
    float wl[SS];
    float wt0 = tmpl[(b * Tc + st) * NP1];
#pragma unroll
    for (int s = 0; s < S; ++s) wl[s] = tmpl[(b * Tc + st) * NP1 + s + 1];

    const float4* dp[SS];
#pragma unroll
    for (int s = 0; s < S; ++s)
        dp[s] = (const float4*)(dec + ((b * Nc + s) * Mc + sm) * Vc);

    for (int i = tid; i < NV4; i += THR) {
        float ax = 0.f, ay = 0.f, az = 0.f, aw = 0.f;
#pragma unroll
        for (int s = 0; s < S; ++s) {
            float4 d = __ldcs(&dp[s][i]);
            ax = fmaf(wl[s], d.x, ax);
            ay = fmaf(wl[s], d.y, ay);
            az = fmaf(wl[s], d.z, az);
            aw = fmaf(wl[s], d.w, aw);
        }
        if (sm == 0 && i == 0) ax += wt0;   // pad one-hot
        float4 r; r.x = ax; r.y = ay; r.z = az; r.w = aw;
        __stcs(&o[i], r);
    }
}

__global__ __launch_bounds__(THR) void k_fix(
    const float* __restrict__ dec,
    const float* __restrict__ tmpl,
    const int*   __restrict__ spans,
    float*       __restrict__ out)
{
    int b = blockIdx.x >> 6;
    int m = blockIdx.x & 63;
    int tid = threadIdx.x;

    __shared__ int s_st, s_sm;

    if (tid < 32) {
        int lane = tid;
        int srct0 = -1, srcm0 = 0;      // row m = lane
        int srct1 = -1, srcm1 = 0;      // row m = lane + 32
        int idx = 0;

        for (int t = 0; t < Tc; ++t) {
            const int4* p0 = (const int4*)&g_any[((b * Tc + t) * Mc + lane) * CH];
            const int4* p1 = (const int4*)&g_any[((b * Tc + t) * Mc + lane + 32) * CH];
            int4 a0 = p0[0], a1 = p0[1];
            int4 c0 = p1[0], c1 = p1[1];
            int nz0 = a0.x | a0.y | a0.z | a0.w | a1.x | a1.y | a1.z | a1.w;
            int nz1 = c0.x | c0.y | c0.z | c0.w | c1.x | c1.y | c1.z | c1.w;
            unsigned z0 = __ballot_sync(0xffffffffu, !nz0);  // iszero, m=0..31
            unsigned z1 = __ballot_sync(0xffffffffu, !nz1);  // iszero, m=32..63
            int len;
            if (z0) len = __ffs(z0) - 1;
            else if (z1) len = 32 + __ffs(z1) - 1;
            else len = Mc;
            int rem = Mc - idx;
            if (len > rem) len = rem;
            int m0 = lane, m1 = lane + 32;
            if (m0 >= idx && m0 < idx + len) { srct0 = t; srcm0 = m0 - idx; }
            if (m1 >= idx && m1 < idx + len) { srct1 = t; srcm1 = m1 - idx; }
            idx += len;
        }
        if (lane == (m & 31)) {
            if (m < 32) { s_st = srct0; s_sm = srcm0; }
            else        { s_st = srct1; s_sm = srcm1; }
        }
    }
    __syncthreads();

    int st = s_st, sm = s_sm;
    if (st == 0 && sm == m) return;     // common case: out_0 already in place

    float4* o = (float4*)(out + (b * Mc + m) * Vc);
    if (st < 0) {
        float4 z; z.x = z.y = z.z = z.w = 0.f;
        for (int i = tid; i < NV4; i += THR) __stcs(&o[i], z);
        return;
    }
    switch (spans[b]) {
        case 0: row_body<0>(dec, tmpl, b, st, sm, o, tid); break;
        case 1: row_body<1>(dec, tmpl, b, st, sm, o, tid); break;
        case 2: row_body<2>(dec, tmpl, b, st, sm, o, tid); break;
        case 3: row_body<3>(dec, tmpl, b, st, sm, o, tid); break;
        case 4: row_body<4>(dec, tmpl, b, st, sm, o, tid); break;
        default: row_body<5>(dec, tmpl, b, st, sm, o, tid); break;
    }
}

// ---------------------------------------------------------------------------
extern "C" void kernel_launch(void* const* d_in, const int* in_sizes, int n_in,
                              void* d_out, int out_size)
{
    const float* dec   = (const float*)d_in[0];   // [B,N,M,V] fp32
    const float* tmpl  = (const float*)d_in[1];   // [B,T,N+1] fp32
    const int*   spans = (const int*)d_in[2];     // [B] int32
    float*       out   = (float*)d_out;           // [B,M,V] fp32

    k_amax<<<Bc * Mc * CH, THR>>>(dec, tmpl, spans, out);
    k_fix <<<Bc * Mc, THR>>>(dec, tmpl, spans, out);
}

// round 7
// speedup vs baseline: 1.0126x; 1.0126x over previous
#include <cuda_runtime.h>

// Problem constants (fixed by the dataset)
#define Bc   8
#define Nc   6
#define Mc   64
#define Vc   32000
#define Tc   8
#define NP1  7            // N+1 template span dim
#define NV4  (Vc/4)       // 8000 float4 per row
#define CH   8            // V chunks per (b,m)
#define CHUNK (NV4/CH)    // 1000 float4 per chunk
#define THR  256
#define SMAX 5            // spans in [0,5]

// Tiny scratch (device globals — no allocation allowed).
// g_any is written unconditionally by every chunk each run -> no init needed.
__device__ int g_any[Bc * Tc * Mc * CH];  // 1 if chunk saw out_v > out0 for (b,t,m,c)

// ---- packed f32x2 helpers (FFMA2 only reachable via PTX) --------------------
__device__ __forceinline__ unsigned long long pk2(float v) {
    unsigned long long r;
    asm("mov.b64 %0, {%1, %1};" : "=l"(r) : "f"(v));
    return r;
}
__device__ __forceinline__ unsigned long long fma2(
    unsigned long long a, unsigned long long b, unsigned long long c) {
    unsigned long long d;
    asm("fma.rn.f32x2 %0, %1, %2, %3;" : "=l"(d) : "l"(a), "l"(b), "l"(c));
    return d;
}
__device__ __forceinline__ float2 up2(unsigned long long a) {
    float2 f;
    asm("mov.b64 {%0, %1}, %2;" : "=f"(f.x), "=f"(f.y) : "l"(a));
    return f;
}
__device__ __forceinline__ ulonglong2 ldcs_u2(const ulonglong2* p) {
    ulonglong2 v;
    asm("ld.global.cs.v2.u64 {%0, %1}, [%2];" : "=l"(v.x), "=l"(v.y) : "l"(p));
    return v;
}

// ---------------------------------------------------------------------------
// Kernel 1: per (b,m,chunk) stream dec once (packed f32x2 math, weights as
// packed u64 in shared), write out_0 to d_out, flag any out_v > out0 per t.
// ---------------------------------------------------------------------------
template <int S>
__device__ __forceinline__ void amax_body(
    const float* __restrict__ dec,
    const unsigned long long (*__restrict__ wpk)[SMAX],  // shared packed (w,w)
    const float* __restrict__ w0,                        // shared [T]
    const float* __restrict__ out0,                      // shared [T]
    int* smask,
    int b, int m, int c, int tid,
    float* __restrict__ out)
{
    constexpr int SS = (S > 0) ? S : 1;

    const ulonglong2* dp[SS];
#pragma unroll
    for (int s = 0; s < S; ++s)
        dp[s] = (const ulonglong2*)(dec + ((b * Nc + s) * Mc + m) * Vc);
    float4* o = (float4*)(out + (b * Mc + m) * Vc);

    const int base = c * CHUNK;
    unsigned mask = 0;

    int i = tid;
    // main loop: 2 float4 elements per trip, 2*S LDG.128 front-batched
    for (; i + THR < CHUNK; i += 2 * THR) {
        int g0 = base + i;
        int g1 = g0 + THR;
        ulonglong2 da[SS], db[SS];
#pragma unroll
        for (int s = 0; s < S; ++s) da[s] = ldcs_u2(&dp[s][g0]);
#pragma unroll
        for (int s = 0; s < S; ++s) db[s] = ldcs_u2(&dp[s][g1]);

#pragma unroll
        for (int t = 0; t < Tc; ++t) {
            unsigned long long a01 = 0ull, a23 = 0ull, b01 = 0ull, b23 = 0ull;
#pragma unroll
            for (int s = 0; s < S; ++s) {
                unsigned long long w2 = wpk[t][s];    // LDS.64 broadcast, 4x reuse
                a01 = fma2(w2, da[s].x, a01);
                a23 = fma2(w2, da[s].y, a23);
                b01 = fma2(w2, db[s].x, b01);
                b23 = fma2(w2, db[s].y, b23);
            }
            float2 A0 = up2(a01), A1 = up2(a23), B0 = up2(b01), B1 = up2(b23);
            float ax = A0.x;
            if (m == 0 && g0 == 0) ax += w0[t];       // pad one-hot (chunk0 tid0)
            if (t == 0) {
                float4 r; r.x = ax; r.y = A0.y; r.z = A1.x; r.w = A1.y;
                __stcs(&o[g0], r);
                float4 q; q.x = B0.x; q.y = B0.y; q.z = B1.x; q.w = B1.y;
                __stcs(&o[g1], q);
            }
            float m1 = fmaxf(fmaxf(fmaxf(ax, A0.y), fmaxf(A1.x, A1.y)),
                             fmaxf(fmaxf(B0.x, B0.y), fmaxf(B1.x, B1.y)));
            mask |= (m1 > out0[t]) ? (1u << t) : 0u;
        }
    }
    // tail: at most one element left per thread
    if (i < CHUNK) {
        int gi = base + i;
        ulonglong2 da[SS];
#pragma unroll
        for (int s = 0; s < S; ++s) da[s] = ldcs_u2(&dp[s][gi]);
#pragma unroll
        for (int t = 0; t < Tc; ++t) {
            unsigned long long a01 = 0ull, a23 = 0ull;
#pragma unroll
            for (int s = 0; s < S; ++s) {
                unsigned long long w2 = wpk[t][s];
                a01 = fma2(w2, da[s].x, a01);
                a23 = fma2(w2, da[s].y, a23);
            }
            float2 A0 = up2(a01), A1 = up2(a23);
            float ax = A0.x;
            if (m == 0 && gi == 0) ax += w0[t];
            if (t == 0) {
                float4 r; r.x = ax; r.y = A0.y; r.z = A1.x; r.w = A1.y;
                __stcs(&o[gi], r);
            }
            float m1 = fmaxf(fmaxf(ax, A0.y), fmaxf(A1.x, A1.y));
            mask |= (m1 > out0[t]) ? (1u << t) : 0u;
        }
    }

    unsigned wm = __reduce_or_sync(0xffffffffu, mask);
    if ((tid & 31) == 0) atomicOr(smask, (int)wm);
    __syncthreads();
    if (tid < Tc)
        g_any[((b * Tc + tid) * Mc + m) * CH + c] = (*smask >> tid) & 1;
}

__global__ __launch_bounds__(THR, 3) void k_amax(
    const float* __restrict__ dec,
    const float* __restrict__ tmpl,
    const int*   __restrict__ spans,
    float*       __restrict__ out)
{
    int bid = blockIdx.x;
    int c = bid & (CH - 1);
    int m = (bid >> 3) & (Mc - 1);
    int b = bid >> 9;
    int tid = threadIdx.x;

    __shared__ unsigned long long wpk[Tc][SMAX];
    __shared__ float w0s[Tc];
    __shared__ float out0s[Tc];
    __shared__ int smask;
    if (tid == 0) smask = 0;

    int S = spans[b];   // 0..5, uniform per block

    // packed masked weights: wpk[t][s] = (w,w) for template col s+1
    if (tid < Tc * SMAX) {
        int t = tid / SMAX, s = tid % SMAX;
        float wv = (s < S) ? tmpl[(b * Tc + t) * NP1 + s + 1] : 0.f;
        wpk[t][s] = pk2(wv);
    }
    if (tid >= Tc * SMAX && tid < Tc * SMAX + Tc)
        w0s[tid - Tc * SMAX] = tmpl[(b * Tc + (tid - Tc * SMAX)) * NP1];
    __syncthreads();

    // out0[t] — scalar fmaf chain, per-lane identical to the fma.rn.f32x2
    // chain, so the v=0 element in chunk 0 compares exactly equal.
    if (tid < Tc) {
        int t = tid;
        float a = 0.f;
        for (int s = 0; s < S; ++s) {
            float wv = tmpl[(b * Tc + t) * NP1 + s + 1];
            a = fmaf(wv, dec[((b * Nc + s) * Mc + m) * Vc], a);
        }
        if (m == 0) a += w0s[t];
        out0s[t] = a;
    }
    __syncthreads();

    switch (S) {
        case 0: amax_body<0>(dec, wpk, w0s, out0s, &smask, b, m, c, tid, out); break;
        case 1: amax_body<1>(dec, wpk, w0s, out0s, &smask, b, m, c, tid, out); break;
        case 2: amax_body<2>(dec, wpk, w0s, out0s, &smask, b, m, c, tid, out); break;
        case 3: amax_body<3>(dec, wpk, w0s, out0s, &smask, b, m, c, tid, out); break;
        case 4: amax_body<4>(dec, wpk, w0s, out0s, &smask, b, m, c, tid, out); break;
        default: amax_body<5>(dec, wpk, w0s, out0s, &smask, b, m, c, tid, out); break;
    }
}

// ---------------------------------------------------------------------------
// Kernel 2: fixup. Warp 0 checks the step-0 identity condition first (one L2
// round trip); the full serial scan runs only for non-identity rows (rare).
// ---------------------------------------------------------------------------
template <int S>
__device__ __forceinline__ void row_body(
    const float* __restrict__ dec,
    const float* __restrict__ tmpl,
    int b, int st, int sm, float4* __restrict__ o, int tid)
{
    constexpr int SS = (S > 0) ? S : 1;
    float wl[SS];
    float wt0 = tmpl[(b * Tc + st) * NP1];
#pragma unroll
    for (int s = 0; s < S; ++s) wl[s] = tmpl[(b * Tc + st) * NP1 + s + 1];

    const float4* dp[SS];
#pragma unroll
    for (int s = 0; s < S; ++s)
        dp[s] = (const float4*)(dec + ((b * Nc + s) * Mc + sm) * Vc);

    for (int i = tid; i < NV4; i += THR) {
        float ax = 0.f, ay = 0.f, az = 0.f, aw = 0.f;
#pragma unroll
        for (int s = 0; s < S; ++s) {
            float4 d = __ldcs(&dp[s][i]);
            ax = fmaf(wl[s], d.x, ax);
            ay = fmaf(wl[s], d.y, ay);
            az = fmaf(wl[s], d.z, az);
            aw = fmaf(wl[s], d.w, aw);
        }
        if (sm == 0 && i == 0) ax += wt0;   // pad one-hot
        float4 r; r.x = ax; r.y = ay; r.z = az; r.w = aw;
        __stcs(&o[i], r);
    }
}

__global__ __launch_bounds__(THR) void k_fix(
    const float* __restrict__ dec,
    const float* __restrict__ tmpl,
    const int*   __restrict__ spans,
    float*       __restrict__ out)
{
    int b = blockIdx.x >> 6;
    int m = blockIdx.x & 63;
    int tid = threadIdx.x;

    __shared__ int s_st, s_sm;

    if (tid < 32) {
        int lane = tid;
        int st = -1, sm = 0;
        int idx = 0;
        for (int t = 0; t < Tc; ++t) {
            const int4* p0 = (const int4*)&g_any[((b * Tc + t) * Mc + lane) * CH];
            const int4* p1 = (const int4*)&g_any[((b * Tc + t) * Mc + lane + 32) * CH];
            int4 a0 = p0[0], a1 = p0[1];
            int4 c0 = p1[0], c1 = p1[1];
            int nz0 = a0.x | a0.y | a0.z | a0.w | a1.x | a1.y | a1.z | a1.w;
            int nz1 = c0.x | c0.y | c0.z | c0.w | c1.x | c1.y | c1.z | c1.w;
            unsigned z0 = __ballot_sync(0xffffffffu, !nz0);  // iszero, m=0..31
            unsigned z1 = __ballot_sync(0xffffffffu, !nz1);  // iszero, m=32..63
            int len;
            if (z0) len = __ffs(z0) - 1;
            else if (z1) len = 32 + __ffs(z1) - 1;
            else len = Mc;
            int rem = Mc - idx;
            if (len > rem) len = rem;
            if (m < idx + len) { st = t; sm = m - idx; break; }  // warp-uniform
            idx += len;
        }
        if (lane == 0) { s_st = st; s_sm = sm; }
    }
    __syncthreads();

    int st = s_st, sm = s_sm;
    if (st == 0 && sm == m) return;     // common case: out_0 already in place

    float4* o = (float4*)(out + (b * Mc + m) * Vc);
    if (st < 0) {
        float4 z; z.x = z.y = z.z = z.w = 0.f;
        for (int i = tid; i < NV4; i += THR) __stcs(&o[i], z);
        return;
    }
    switch (spans[b]) {
        case 0: row_body<0>(dec, tmpl, b, st, sm, o, tid); break;
        case 1: row_body<1>(dec, tmpl, b, st, sm, o, tid); break;
        case 2: row_body<2>(dec, tmpl, b, st, sm, o, tid); break;
        case 3: row_body<3>(dec, tmpl, b, st, sm, o, tid); break;
        case 4: row_body<4>(dec, tmpl, b, st, sm, o, tid); break;
        default: row_body<5>(dec, tmpl, b, st, sm, o, tid); break;
    }
}

// ---------------------------------------------------------------------------
extern "C" void kernel_launch(void* const* d_in, const int* in_sizes, int n_in,
                              void* d_out, int out_size)
{
    const float* dec   = (const float*)d_in[0];   // [B,N,M,V] fp32
    const float* tmpl  = (const float*)d_in[1];   // [B,T,N+1] fp32
    const int*   spans = (const int*)d_in[2];     // [B] int32
    float*       out   = (float*)d_out;           // [B,M,V] fp32

    k_amax<<<Bc * Mc * CH, THR>>>(dec, tmpl, spans, out);
    k_fix <<<Bc * Mc, THR>>>(dec, tmpl, spans, out);
}